// round 9
// baseline (speedup 1.0000x reference)
#include <cuda_runtime.h>
#include <cuda_fp16.h>
#include <math.h>
#include <stdint.h>

#define NTOK 8192
#define HID  2048
#define DN   512
#define NE   16
#define BKC  64                 // fp16 K per chunk (128B rows)
#define TILE_B 16384            // 128 rows x 128B
#define STAGE_B (2 * TILE_B)    // A, B

// SMEM offsets within dynamic smem
#define SM_META  0              // int[128]
#define SM_P     512            // float[128]
#define SM_TILES 1024
#define SMEM_BYTES (SM_TILES + 2 * STAGE_B)   // 66560

#define SWZ(o) ((o) ^ (((o) >> 3) & 0x70))

// ---------------- PTX helpers (sm_80+ features only) ----------------
__device__ __forceinline__ uint32_t smem_u32(const void* p) {
    uint32_t a;
    asm("{ .reg .u64 t; cvta.to.shared.u64 t, %1; cvt.u32.u64 %0, t; }" : "=r"(a) : "l"(p));
    return a;
}
#define CP16(dst, src) \
    asm volatile("cp.async.cg.shared.global [%0], [%1], 16;" :: "r"(dst), "l"(src) : "memory")
#define CP_COMMIT() asm volatile("cp.async.commit_group;" ::: "memory")
#define CP_WAIT(n)  asm volatile("cp.async.wait_group %0;" :: "n"(n) : "memory")

__device__ __forceinline__ void ldsm_x4(uint32_t& r0, uint32_t& r1, uint32_t& r2, uint32_t& r3,
                                        uint32_t addr) {
    asm volatile("ldmatrix.sync.aligned.m8n8.x4.shared.b16 {%0,%1,%2,%3}, [%4];"
                 : "=r"(r0), "=r"(r1), "=r"(r2), "=r"(r3) : "r"(addr));
}
__device__ __forceinline__ void mma_f16(float* c, const uint32_t* a, uint32_t b0, uint32_t b1) {
    asm volatile("mma.sync.aligned.m16n8k16.row.col.f32.f16.f16.f32 "
                 "{%0,%1,%2,%3}, {%4,%5,%6,%7}, {%8,%9}, {%0,%1,%2,%3};"
                 : "+f"(c[0]), "+f"(c[1]), "+f"(c[2]), "+f"(c[3])
                 : "r"(a[0]), "r"(a[1]), "r"(a[2]), "r"(a[3]), "r"(b0), "r"(b1));
}

// ---------------- scratch (device globals) ----------------
__device__ int    g_count[NE];
__device__ int    g_list [NE * NTOK];     // token | (slot<<16)
__device__ float  g_plist[NE * NTOK];
__device__ int2   g_te[NTOK];
__device__ float2 g_tp[NTOK];
__device__ float  g_slots[2u * NTOK * DN];
__device__ float  g_expsum[NE];

__device__ __half g_xh [NTOK * HID];
__device__ __half g_dwh[NE * DN * HID];
__device__ __half g_uwh[HID * DN];
__device__ __half g_hh [NTOK * DN];

// ---------------- small kernels ----------------
__global__ void zero_counts_kernel() {
    if (threadIdx.x < NE) g_count[threadIdx.x] = 0;
}

__device__ __forceinline__ void conv4h(const float4 v, __half* dst, size_t i4) {
    __half2 a = __floats2half2_rn(v.x, v.y);
    __half2 b = __floats2half2_rn(v.z, v.w);
    ((uint2*)dst)[i4] = make_uint2(*(uint32_t*)&a, *(uint32_t*)&b);
}

__global__ void __launch_bounds__(256) conv_x_kernel(const float* __restrict__ src) {
    size_t i = (size_t)blockIdx.x * blockDim.x + threadIdx.x;
    conv4h(((const float4*)src)[i], g_xh, i);
}
__global__ void __launch_bounds__(256) conv_dw_kernel(const float* __restrict__ src) {
    size_t i = (size_t)blockIdx.x * blockDim.x + threadIdx.x;
    conv4h(((const float4*)src)[i], g_dwh, i);
}
__global__ void __launch_bounds__(256) conv_uw_kernel(const float* __restrict__ src) {
    size_t i = (size_t)blockIdx.x * blockDim.x + threadIdx.x;
    conv4h(((const float4*)src)[i], g_uwh, i);
}

__global__ void __launch_bounds__(128) gate_kernel(const float* __restrict__ x,
                                                   const float* __restrict__ gw) {
    __shared__ float xs[HID];
    __shared__ float logits[NE];
    const int t = blockIdx.x;
    const float* xr = x + (size_t)t * HID;
    for (int i = threadIdx.x; i < HID / 4; i += blockDim.x)
        ((float4*)xs)[i] = ((const float4*)xr)[i];
    __syncthreads();

    const int e = threadIdx.x >> 3;
    const int l = threadIdx.x & 7;
    const float* w = gw + (size_t)e * HID;
    float s = 0.f;
    for (int j = l; j < HID; j += 8) s += xs[j] * __ldg(w + j);
    for (int o = 4; o; o >>= 1) s += __shfl_down_sync(0xffffffffu, s, o, 8);
    if (l == 0) logits[e] = s;
    __syncthreads();

    if (threadIdx.x == 0) {
        float v0 = -1e30f; int i0 = 0;
        #pragma unroll
        for (int k = 0; k < NE; k++) { float v = logits[k]; if (v > v0) { v0 = v; i0 = k; } }
        float v1 = -1e30f; int i1 = 0;
        #pragma unroll
        for (int k = 0; k < NE; k++) { if (k == i0) continue; float v = logits[k]; if (v > v1) { v1 = v; i1 = k; } }
        float z  = expf(v1 - v0);
        float p0 = 1.f / (1.f + z);
        float p1 = z   / (1.f + z);

        int pos0 = atomicAdd(&g_count[i0], 1);
        g_list [i0 * NTOK + pos0] = t;
        g_plist[i0 * NTOK + pos0] = p0;
        int pos1 = atomicAdd(&g_count[i1], 1);
        g_list [i1 * NTOK + pos1] = t | (1 << 16);
        g_plist[i1 * NTOK + pos1] = p1;
        g_te[t] = make_int2(i0, i1);
        g_tp[t] = make_float2(p0, p1);
    }
}

__global__ void __launch_bounds__(256) expsum_kernel() {
    __shared__ float red[256];
    const int e = blockIdx.x;
    float s = 0.f;
    for (int t = threadIdx.x; t < NTOK; t += 256) {
        int2 te = g_te[t]; float2 tp = g_tp[t];
        if (te.x == e) s += tp.x;
        if (te.y == e) s += tp.y;
    }
    red[threadIdx.x] = s; __syncthreads();
    for (int o = 128; o; o >>= 1) {
        if (threadIdx.x < o) red[threadIdx.x] += red[threadIdx.x + o];
        __syncthreads();
    }
    if (threadIdx.x == 0) g_expsum[e] = red[0];
}

__device__ __forceinline__ float gelu_new(float v) {
    return 0.5f * v * (1.f + tanhf(0.7978845608028654f * (v + 0.044715f * v * v * v)));
}

__global__ void __launch_bounds__(256) gelu_kernel() {
    const size_t i = (size_t)blockIdx.x * blockDim.x + threadIdx.x;
    float4 a = ((const float4*)g_slots)[i];
    float4 b = ((const float4*)(g_slots + (size_t)NTOK * DN))[i];
    float4 r;
    r.x = gelu_new(a.x + b.x);
    r.y = gelu_new(a.y + b.y);
    r.z = gelu_new(a.z + b.z);
    r.w = gelu_new(a.w + b.w);
    conv4h(r, g_hh, i);
}

__global__ void loss_kernel(float* out, int out_size) {
    if (out_size > NTOK * HID) {
        float s = 0.f;
        #pragma unroll
        for (int e = 0; e < NE; e++) { float v = g_expsum[e]; s += v * v; }
        out[NTOK * HID] = (float)NE * 0.1f * s / ((float)NTOK * (float)NTOK);
    }
}

// ---------------- HMMA GEMM core ----------------
// Single pass over a 64-K chunk: C += A_tile(128x64) * B_tile(128x64)^T
// 4 warps; warp (wm, wn) owns rows wm*64..+64, cols wn*64..+64.
__device__ __forceinline__ void mma_pass(uint32_t aT, uint32_t bT, int lane, int wm, int wn,
                                         float C[4][8][4]) {
    const int g = lane >> 3, i = lane & 7;
    #pragma unroll
    for (int kk = 0; kk < 4; ++kk) {
        uint32_t af[4][4];
        #pragma unroll
        for (int mt = 0; mt < 4; ++mt) {
            int row  = wm * 64 + mt * 16 + i + (g & 1) * 8;
            int colb = kk * 32 + (g >> 1) * 16;
            ldsm_x4(af[mt][0], af[mt][1], af[mt][2], af[mt][3],
                    aT + SWZ((uint32_t)(row * 128 + colb)));
        }
        uint32_t bf[8][2];
        #pragma unroll
        for (int np = 0; np < 4; ++np) {
            int row  = wn * 64 + np * 16 + i + (g >> 1) * 8;
            int colb = kk * 32 + (g & 1) * 16;
            uint32_t r0, r1, r2, r3;
            ldsm_x4(r0, r1, r2, r3, bT + SWZ((uint32_t)(row * 128 + colb)));
            bf[np * 2][0] = r0; bf[np * 2][1] = r1;
            bf[np * 2 + 1][0] = r2; bf[np * 2 + 1][1] = r3;
        }
        #pragma unroll
        for (int mt = 0; mt < 4; ++mt)
            #pragma unroll
            for (int nt = 0; nt < 8; ++nt)
                mma_f16(C[mt][nt], af[mt], bf[nt][0], bf[nt][1]);
    }
}

// down: per expert e, C[m,n] = p_m * (x[tok_m] . dw[e][n] + db[e][n]) -> g_slots
__global__ void __launch_bounds__(128, 2) down_mma_kernel(const float* __restrict__ db) {
    extern __shared__ __align__(1024) char smem[];
    const int e   = blockIdx.z;
    const int cnt = g_count[e];
    const int m0  = blockIdx.y * 128;
    if (m0 >= cnt) return;
    const int n0  = blockIdx.x * 128;

    const int tid  = threadIdx.x;
    const int lane = tid & 31;
    const int wid  = tid >> 5;
    const int wm   = wid >> 1;          // 0..1
    const int wn   = wid & 1;           // 0..1

    int*   smeta = (int*)(smem + SM_META);
    float* sp    = (float*)(smem + SM_P);
    {
        int m = m0 + tid;
        int v = 0; float p = 0.f;
        if (m < cnt) { v = g_list[e * NTOK + m]; p = g_plist[e * NTOK + m]; }
        smeta[tid] = v;
        sp[tid]    = p;
    }
    __syncthreads();

    const uint32_t sb = smem_u32(smem);
    const uint32_t tiles = sb + SM_TILES;

    auto load_stage = [&](int buf, int k0) {
        uint32_t st = tiles + buf * STAGE_B;
        #pragma unroll
        for (int q = 0; q < 8; ++q) {
            int u = tid + q * 128;
            int row = u >> 3, j = u & 7;
            int tok = smeta[row] & 0xffff;
            size_t src = (size_t)tok * HID + k0 + j * 8;
            uint32_t so = SWZ((uint32_t)(row * 128 + j * 16));
            CP16(st + so,          g_xh + src);
            size_t bsrc = ((size_t)e * DN + n0 + row) * HID + k0 + j * 8;
            CP16(st + TILE_B + so, g_dwh + bsrc);
        }
    };

    float C[4][8][4] = {};
    const int NCH = HID / BKC;   // 32

    load_stage(0, 0);
    CP_COMMIT();
    for (int c = 0; c < NCH; ++c) {
        const int buf = c & 1;
        if (c + 1 < NCH) {
            load_stage(buf ^ 1, (c + 1) * BKC);
            CP_COMMIT();
            CP_WAIT(1);
        } else {
            CP_WAIT(0);
        }
        __syncthreads();
        uint32_t st = tiles + buf * STAGE_B;
        mma_pass(st, st + TILE_B, lane, wm, wn, C);
        __syncthreads();
    }

    // epilogue
    const float* dbp = db + (size_t)e * DN + n0 + wn * 64;
    #pragma unroll
    for (int mt = 0; mt < 4; ++mt) {
        #pragma unroll
        for (int half = 0; half < 2; ++half) {
            int rl = wm * 64 + mt * 16 + (lane >> 2) + half * 8;
            if (m0 + rl < cnt) {
                int   meta = smeta[rl];
                float p    = sp[rl];
                int tok = meta & 0xffff, slot = meta >> 16;
                float* dst = g_slots + ((size_t)slot * NTOK + tok) * DN + n0 + wn * 64;
                #pragma unroll
                for (int nt = 0; nt < 8; ++nt) {
                    int col = nt * 8 + (lane & 3) * 2;
                    float2 v;
                    v.x = p * (C[mt][nt][half * 2 + 0] + __ldg(dbp + col));
                    v.y = p * (C[mt][nt][half * 2 + 1] + __ldg(dbp + col + 1));
                    *(float2*)(dst + col) = v;
                }
            }
        }
    }
}

// up: out[m,n] = g_h[m] . up_w[n] + ub[n]   (M=8192, N=2048, K=512)
__global__ void __launch_bounds__(128, 2) up_mma_kernel(const float* __restrict__ ub,
                                                        float* __restrict__ out) {
    extern __shared__ __align__(1024) char smem[];
    const int m0 = blockIdx.y * 128;
    const int n0 = blockIdx.x * 128;

    const int tid  = threadIdx.x;
    const int lane = tid & 31;
    const int wid  = tid >> 5;
    const int wm   = wid >> 1;
    const int wn   = wid & 1;

    const uint32_t sb = smem_u32(smem);
    const uint32_t tiles = sb + SM_TILES;

    auto load_stage = [&](int buf, int k0) {
        uint32_t st = tiles + buf * STAGE_B;
        #pragma unroll
        for (int q = 0; q < 8; ++q) {
            int u = tid + q * 128;
            int row = u >> 3, j = u & 7;
            size_t asrc = (size_t)(m0 + row) * DN + k0 + j * 8;
            size_t bsrc = (size_t)(n0 + row) * DN + k0 + j * 8;
            uint32_t so = SWZ((uint32_t)(row * 128 + j * 16));
            CP16(st + so,          g_hh + asrc);
            CP16(st + TILE_B + so, g_uwh + bsrc);
        }
    };

    float C[4][8][4] = {};
    const int NCH = DN / BKC;   // 8

    load_stage(0, 0);
    CP_COMMIT();
    for (int c = 0; c < NCH; ++c) {
        const int buf = c & 1;
        if (c + 1 < NCH) {
            load_stage(buf ^ 1, (c + 1) * BKC);
            CP_COMMIT();
            CP_WAIT(1);
        } else {
            CP_WAIT(0);
        }
        __syncthreads();
        uint32_t st = tiles + buf * STAGE_B;
        mma_pass(st, st + TILE_B, lane, wm, wn, C);
        __syncthreads();
    }

    const float* ubp = ub + n0 + wn * 64;
    #pragma unroll
    for (int mt = 0; mt < 4; ++mt) {
        #pragma unroll
        for (int half = 0; half < 2; ++half) {
            int rl = wm * 64 + mt * 16 + (lane >> 2) + half * 8;
            float* dst = out + (size_t)(m0 + rl) * HID + n0 + wn * 64;
            #pragma unroll
            for (int nt = 0; nt < 8; ++nt) {
                int col = nt * 8 + (lane & 3) * 2;
                float2 v;
                v.x = C[mt][nt][half * 2 + 0] + __ldg(ubp + col);
                v.y = C[mt][nt][half * 2 + 1] + __ldg(ubp + col + 1);
                *(float2*)(dst + col) = v;
            }
        }
    }
}

// ---------------- launch ----------------
extern "C" void kernel_launch(void* const* d_in, const int* in_sizes, int n_in,
                              void* d_out, int out_size) {
    const float* x      = (const float*)d_in[0];
    const float* gate_w = (const float*)d_in[1];
    const float* down_w = (const float*)d_in[2];
    const float* down_b = (const float*)d_in[3];
    const float* up_w   = (const float*)d_in[4];
    const float* up_b   = (const float*)d_in[5];
    float* out = (float*)d_out;

    cudaFuncSetAttribute(down_mma_kernel, cudaFuncAttributeMaxDynamicSharedMemorySize, SMEM_BYTES);
    cudaFuncSetAttribute(up_mma_kernel,   cudaFuncAttributeMaxDynamicSharedMemorySize, SMEM_BYTES);

    zero_counts_kernel<<<1, 32>>>();
    conv_x_kernel <<<(NTOK * HID / 4) / 256, 256>>>(x);
    conv_dw_kernel<<<(NE * DN * HID / 4) / 256, 256>>>(down_w);
    conv_uw_kernel<<<(HID * DN / 4) / 256, 256>>>(up_w);
    gate_kernel<<<NTOK, 128>>>(x, gate_w);
    expsum_kernel<<<NE, 256>>>();
    down_mma_kernel<<<dim3(DN / 128, NTOK / 128, NE), 128, SMEM_BYTES>>>(down_b);
    gelu_kernel<<<(NTOK * DN / 4) / 256, 256>>>();
    up_mma_kernel<<<dim3(HID / 128, NTOK / 128), 128, SMEM_BYTES>>>(up_b, out);
    loss_kernel<<<1, 1>>>(out, out_size);
}

// round 10
// speedup vs baseline: 1.0579x; 1.0579x over previous
#include <cuda_runtime.h>
#include <cuda_fp16.h>
#include <math.h>
#include <stdint.h>

#define NTOK 8192
#define HID  2048
#define DN   512
#define NE   16
#define BKC  64                 // fp16 K per chunk (128B rows)
#define TILE_B 16384            // 128 rows x 128B
#define STAGE_B (2 * TILE_B)    // A, B
#define NSTAGE 3

// SMEM offsets within dynamic smem
#define SM_META  0              // int[128]
#define SM_P     512            // float[128]
#define SM_TILES 1024
#define SMEM_BYTES (SM_TILES + NSTAGE * STAGE_B)   // 99328

#define SWZ(o) ((o) ^ (((o) >> 3) & 0x70))

// ---------------- PTX helpers (sm_80+ features only) ----------------
__device__ __forceinline__ uint32_t smem_u32(const void* p) {
    uint32_t a;
    asm("{ .reg .u64 t; cvta.to.shared.u64 t, %1; cvt.u32.u64 %0, t; }" : "=r"(a) : "l"(p));
    return a;
}
#define CP16(dst, src) \
    asm volatile("cp.async.cg.shared.global [%0], [%1], 16;" :: "r"(dst), "l"(src) : "memory")
#define CP_COMMIT() asm volatile("cp.async.commit_group;" ::: "memory")
#define CP_WAIT(n)  asm volatile("cp.async.wait_group %0;" :: "n"(n) : "memory")

__device__ __forceinline__ void ldsm_x4(uint32_t& r0, uint32_t& r1, uint32_t& r2, uint32_t& r3,
                                        uint32_t addr) {
    asm volatile("ldmatrix.sync.aligned.m8n8.x4.shared.b16 {%0,%1,%2,%3}, [%4];"
                 : "=r"(r0), "=r"(r1), "=r"(r2), "=r"(r3) : "r"(addr));
}
__device__ __forceinline__ void mma_f16(float* c, const uint32_t* a, uint32_t b0, uint32_t b1) {
    asm volatile("mma.sync.aligned.m16n8k16.row.col.f32.f16.f16.f32 "
                 "{%0,%1,%2,%3}, {%4,%5,%6,%7}, {%8,%9}, {%0,%1,%2,%3};"
                 : "+f"(c[0]), "+f"(c[1]), "+f"(c[2]), "+f"(c[3])
                 : "r"(a[0]), "r"(a[1]), "r"(a[2]), "r"(a[3]), "r"(b0), "r"(b1));
}

// ---------------- scratch (device globals) ----------------
__device__ int    g_count[NE];
__device__ int    g_list [NE * NTOK];     // token | (slot<<16)
__device__ float  g_plist[NE * NTOK];
__device__ int2   g_te[NTOK];
__device__ float2 g_tp[NTOK];
__device__ float  g_slots[2u * NTOK * DN];
__device__ float  g_expsum[NE];

__device__ __half g_xh [NTOK * HID];
__device__ __half g_dwh[NE * DN * HID];
__device__ __half g_uwh[HID * DN];
__device__ __half g_hh [NTOK * DN];

// ---------------- small kernels ----------------
__global__ void zero_counts_kernel() {
    if (threadIdx.x < NE) g_count[threadIdx.x] = 0;
}

__device__ __forceinline__ void conv4h(const float4 v, __half* dst, size_t i4) {
    __half2 a = __floats2half2_rn(v.x, v.y);
    __half2 b = __floats2half2_rn(v.z, v.w);
    ((uint2*)dst)[i4] = make_uint2(*(uint32_t*)&a, *(uint32_t*)&b);
}

__global__ void __launch_bounds__(256) conv_dw_kernel(const float* __restrict__ src) {
    size_t i = (size_t)blockIdx.x * blockDim.x + threadIdx.x;
    conv4h(((const float4*)src)[i], g_dwh, i);
}
__global__ void __launch_bounds__(256) conv_uw_kernel(const float* __restrict__ src) {
    size_t i = (size_t)blockIdx.x * blockDim.x + threadIdx.x;
    conv4h(((const float4*)src)[i], g_uwh, i);
}

// gate + fused x->fp16 conversion (x is staged through SMEM anyway)
__global__ void __launch_bounds__(128) gate_kernel(const float* __restrict__ x,
                                                   const float* __restrict__ gw) {
    __shared__ float xs[HID];
    __shared__ float logits[NE];
    const int t = blockIdx.x;
    const float* xr = x + (size_t)t * HID;
    __half* xh = g_xh + (size_t)t * HID;
    for (int i = threadIdx.x; i < HID / 4; i += blockDim.x) {
        float4 v = ((const float4*)xr)[i];
        ((float4*)xs)[i] = v;
        conv4h(v, xh, i);
    }
    __syncthreads();

    const int e = threadIdx.x >> 3;
    const int l = threadIdx.x & 7;
    const float* w = gw + (size_t)e * HID;
    float s = 0.f;
    for (int j = l; j < HID; j += 8) s += xs[j] * __ldg(w + j);
    for (int o = 4; o; o >>= 1) s += __shfl_down_sync(0xffffffffu, s, o, 8);
    if (l == 0) logits[e] = s;
    __syncthreads();

    if (threadIdx.x == 0) {
        float v0 = -1e30f; int i0 = 0;
        #pragma unroll
        for (int k = 0; k < NE; k++) { float v = logits[k]; if (v > v0) { v0 = v; i0 = k; } }
        float v1 = -1e30f; int i1 = 0;
        #pragma unroll
        for (int k = 0; k < NE; k++) { if (k == i0) continue; float v = logits[k]; if (v > v1) { v1 = v; i1 = k; } }
        float z  = expf(v1 - v0);
        float p0 = 1.f / (1.f + z);
        float p1 = z   / (1.f + z);

        int pos0 = atomicAdd(&g_count[i0], 1);
        g_list [i0 * NTOK + pos0] = t;
        g_plist[i0 * NTOK + pos0] = p0;
        int pos1 = atomicAdd(&g_count[i1], 1);
        g_list [i1 * NTOK + pos1] = t | (1 << 16);
        g_plist[i1 * NTOK + pos1] = p1;
        g_te[t] = make_int2(i0, i1);
        g_tp[t] = make_float2(p0, p1);
    }
}

__global__ void __launch_bounds__(256) expsum_kernel() {
    __shared__ float red[256];
    const int e = blockIdx.x;
    float s = 0.f;
    for (int t = threadIdx.x; t < NTOK; t += 256) {
        int2 te = g_te[t]; float2 tp = g_tp[t];
        if (te.x == e) s += tp.x;
        if (te.y == e) s += tp.y;
    }
    red[threadIdx.x] = s; __syncthreads();
    for (int o = 128; o; o >>= 1) {
        if (threadIdx.x < o) red[threadIdx.x] += red[threadIdx.x + o];
        __syncthreads();
    }
    if (threadIdx.x == 0) g_expsum[e] = red[0];
}

__device__ __forceinline__ float gelu_new(float v) {
    return 0.5f * v * (1.f + tanhf(0.7978845608028654f * (v + 0.044715f * v * v * v)));
}

__global__ void __launch_bounds__(256) gelu_kernel() {
    const size_t i = (size_t)blockIdx.x * blockDim.x + threadIdx.x;
    float4 a = ((const float4*)g_slots)[i];
    float4 b = ((const float4*)(g_slots + (size_t)NTOK * DN))[i];
    float4 r;
    r.x = gelu_new(a.x + b.x);
    r.y = gelu_new(a.y + b.y);
    r.z = gelu_new(a.z + b.z);
    r.w = gelu_new(a.w + b.w);
    conv4h(r, g_hh, i);
}

__global__ void loss_kernel(float* out, int out_size) {
    if (out_size > NTOK * HID) {
        float s = 0.f;
        #pragma unroll
        for (int e = 0; e < NE; e++) { float v = g_expsum[e]; s += v * v; }
        out[NTOK * HID] = (float)NE * 0.1f * s / ((float)NTOK * (float)NTOK);
    }
}

// ---------------- HMMA GEMM core ----------------
// Single pass over a 64-K chunk: C += A_tile(128x64) * B_tile(128x64)^T
// 8 warps; warp (wm, wn) owns rows wm*32..+32, cols wn*64..+64.
__device__ __forceinline__ void mma_pass(uint32_t aT, uint32_t bT, int lane, int wm, int wn,
                                         float C[2][8][4]) {
    const int g = lane >> 3, i = lane & 7;
    #pragma unroll
    for (int kk = 0; kk < 4; ++kk) {
        uint32_t af[2][4];
        #pragma unroll
        for (int mt = 0; mt < 2; ++mt) {
            int row  = wm * 32 + mt * 16 + i + (g & 1) * 8;
            int colb = kk * 32 + (g >> 1) * 16;
            ldsm_x4(af[mt][0], af[mt][1], af[mt][2], af[mt][3],
                    aT + SWZ((uint32_t)(row * 128 + colb)));
        }
        uint32_t bf[8][2];
        #pragma unroll
        for (int np = 0; np < 4; ++np) {
            int row  = wn * 64 + np * 16 + i + (g >> 1) * 8;
            int colb = kk * 32 + (g & 1) * 16;
            uint32_t r0, r1, r2, r3;
            ldsm_x4(r0, r1, r2, r3, bT + SWZ((uint32_t)(row * 128 + colb)));
            bf[np * 2][0] = r0; bf[np * 2][1] = r1;
            bf[np * 2 + 1][0] = r2; bf[np * 2 + 1][1] = r3;
        }
        #pragma unroll
        for (int mt = 0; mt < 2; ++mt)
            #pragma unroll
            for (int nt = 0; nt < 8; ++nt)
                mma_f16(C[mt][nt], af[mt], bf[nt][0], bf[nt][1]);
    }
}

// down: per expert e, C[m,n] = p_m * (x[tok_m] . dw[e][n] + db[e][n]) -> g_slots
__global__ void __launch_bounds__(256) down_mma_kernel(const float* __restrict__ db) {
    extern __shared__ __align__(1024) char smem[];
    const int e   = blockIdx.z;
    const int cnt = g_count[e];
    const int m0  = blockIdx.y * 128;
    if (m0 >= cnt) return;
    const int n0  = blockIdx.x * 128;

    const int tid  = threadIdx.x;
    const int lane = tid & 31;
    const int wid  = tid >> 5;
    const int wm   = wid >> 1;          // 0..3
    const int wn   = wid & 1;           // 0..1

    int*   smeta = (int*)(smem + SM_META);
    float* sp    = (float*)(smem + SM_P);
    if (tid < 128) {
        int m = m0 + tid;
        int v = 0; float p = 0.f;
        if (m < cnt) { v = g_list[e * NTOK + m]; p = g_plist[e * NTOK + m]; }
        smeta[tid] = v;
        sp[tid]    = p;
    }
    __syncthreads();

    const uint32_t sb = smem_u32(smem);
    const uint32_t tiles = sb + SM_TILES;

    auto load_stage = [&](int buf, int k0) {
        uint32_t st = tiles + buf * STAGE_B;
        #pragma unroll
        for (int q = 0; q < 4; ++q) {
            int u = tid + q * 256;
            int row = u >> 3, j = u & 7;
            int tok = smeta[row] & 0xffff;
            size_t src = (size_t)tok * HID + k0 + j * 8;
            uint32_t so = SWZ((uint32_t)(row * 128 + j * 16));
            CP16(st + so,          g_xh + src);
            size_t bsrc = ((size_t)e * DN + n0 + row) * HID + k0 + j * 8;
            CP16(st + TILE_B + so, g_dwh + bsrc);
        }
    };

    float C[2][8][4] = {};
    const int NCH = HID / BKC;   // 32

    load_stage(0, 0);
    CP_COMMIT();
    load_stage(1, BKC);
    CP_COMMIT();
    for (int c = 0; c < NCH; ++c) {
        if (c < NCH - 1) { CP_WAIT(1); } else { CP_WAIT(0); }
        __syncthreads();   // data(c) visible to all; all warps done reading buf[(c+2)%3]
        if (c + 2 < NCH) {
            load_stage((c + 2) % NSTAGE, (c + 2) * BKC);
            CP_COMMIT();
        }
        uint32_t st = tiles + (c % NSTAGE) * STAGE_B;
        mma_pass(st, st + TILE_B, lane, wm, wn, C);
    }

    // epilogue
    const float* dbp = db + (size_t)e * DN + n0 + wn * 64;
    #pragma unroll
    for (int mt = 0; mt < 2; ++mt) {
        #pragma unroll
        for (int half = 0; half < 2; ++half) {
            int rl = wm * 32 + mt * 16 + (lane >> 2) + half * 8;
            if (m0 + rl < cnt) {
                int   meta = smeta[rl];
                float p    = sp[rl];
                int tok = meta & 0xffff, slot = meta >> 16;
                float* dst = g_slots + ((size_t)slot * NTOK + tok) * DN + n0 + wn * 64;
                #pragma unroll
                for (int nt = 0; nt < 8; ++nt) {
                    int col = nt * 8 + (lane & 3) * 2;
                    float2 v;
                    v.x = p * (C[mt][nt][half * 2 + 0] + __ldg(dbp + col));
                    v.y = p * (C[mt][nt][half * 2 + 1] + __ldg(dbp + col + 1));
                    *(float2*)(dst + col) = v;
                }
            }
        }
    }
}

// up: out[m,n] = g_h[m] . up_w[n] + ub[n]   (M=8192, N=2048, K=512)
__global__ void __launch_bounds__(256) up_mma_kernel(const float* __restrict__ ub,
                                                     float* __restrict__ out) {
    extern __shared__ __align__(1024) char smem[];
    const int m0 = blockIdx.y * 128;
    const int n0 = blockIdx.x * 128;

    const int tid  = threadIdx.x;
    const int lane = tid & 31;
    const int wid  = tid >> 5;
    const int wm   = wid >> 1;
    const int wn   = wid & 1;

    const uint32_t sb = smem_u32(smem);
    const uint32_t tiles = sb + SM_TILES;

    auto load_stage = [&](int buf, int k0) {
        uint32_t st = tiles + buf * STAGE_B;
        #pragma unroll
        for (int q = 0; q < 4; ++q) {
            int u = tid + q * 256;
            int row = u >> 3, j = u & 7;
            size_t asrc = (size_t)(m0 + row) * DN + k0 + j * 8;
            size_t bsrc = (size_t)(n0 + row) * DN + k0 + j * 8;
            uint32_t so = SWZ((uint32_t)(row * 128 + j * 16));
            CP16(st + so,          g_hh + asrc);
            CP16(st + TILE_B + so, g_uwh + bsrc);
        }
    };

    float C[2][8][4] = {};
    const int NCH = DN / BKC;   // 8

    load_stage(0, 0);
    CP_COMMIT();
    load_stage(1, BKC);
    CP_COMMIT();
    for (int c = 0; c < NCH; ++c) {
        if (c < NCH - 1) { CP_WAIT(1); } else { CP_WAIT(0); }
        __syncthreads();
        if (c + 2 < NCH) {
            load_stage((c + 2) % NSTAGE, (c + 2) * BKC);
            CP_COMMIT();
        }
        uint32_t st = tiles + (c % NSTAGE) * STAGE_B;
        mma_pass(st, st + TILE_B, lane, wm, wn, C);
    }

    const float* ubp = ub + n0 + wn * 64;
    #pragma unroll
    for (int mt = 0; mt < 2; ++mt) {
        #pragma unroll
        for (int half = 0; half < 2; ++half) {
            int rl = wm * 32 + mt * 16 + (lane >> 2) + half * 8;
            float* dst = out + (size_t)(m0 + rl) * HID + n0 + wn * 64;
            #pragma unroll
            for (int nt = 0; nt < 8; ++nt) {
                int col = nt * 8 + (lane & 3) * 2;
                float2 v;
                v.x = C[mt][nt][half * 2 + 0] + __ldg(ubp + col);
                v.y = C[mt][nt][half * 2 + 1] + __ldg(ubp + col + 1);
                *(float2*)(dst + col) = v;
            }
        }
    }
}

// ---------------- launch ----------------
extern "C" void kernel_launch(void* const* d_in, const int* in_sizes, int n_in,
                              void* d_out, int out_size) {
    const float* x      = (const float*)d_in[0];
    const float* gate_w = (const float*)d_in[1];
    const float* down_w = (const float*)d_in[2];
    const float* down_b = (const float*)d_in[3];
    const float* up_w   = (const float*)d_in[4];
    const float* up_b   = (const float*)d_in[5];
    float* out = (float*)d_out;

    cudaFuncSetAttribute(down_mma_kernel, cudaFuncAttributeMaxDynamicSharedMemorySize, SMEM_BYTES);
    cudaFuncSetAttribute(up_mma_kernel,   cudaFuncAttributeMaxDynamicSharedMemorySize, SMEM_BYTES);

    zero_counts_kernel<<<1, 32>>>();
    conv_dw_kernel<<<(NE * DN * HID / 4) / 256, 256>>>(down_w);
    conv_uw_kernel<<<(HID * DN / 4) / 256, 256>>>(up_w);
    gate_kernel<<<NTOK, 128>>>(x, gate_w);
    expsum_kernel<<<NE, 256>>>();
    down_mma_kernel<<<dim3(DN / 128, NTOK / 128, NE), 256, SMEM_BYTES>>>(down_b);
    gelu_kernel<<<(NTOK * DN / 4) / 256, 256>>>();
    up_mma_kernel<<<dim3(HID / 128, NTOK / 128), 256, SMEM_BYTES>>>(up_b, out);
    loss_kernel<<<1, 1>>>(out, out_size);
}

// round 13
// speedup vs baseline: 1.0622x; 1.0041x over previous
#include <cuda_runtime.h>
#include <cuda_fp16.h>
#include <math.h>
#include <stdint.h>

#define NTOK 8192
#define HID  2048
#define DN   512
#define NE   16
#define BKC  64                 // fp16 K per chunk (128B rows)
#define TILE_B 16384            // 128 rows x 128B
#define STAGE_B (2 * TILE_B)    // A, B
#define NSTAGE 3

// SMEM offsets within dynamic smem
#define SM_META  0              // int[128]
#define SM_P     512            // float[128]
#define SM_TILES 1024
#define SMEM_BYTES (SM_TILES + NSTAGE * STAGE_B)   // 99328

#define SWZ(o) ((o) ^ (((o) >> 3) & 0x70))

// ---------------- PTX helpers (sm_80+ features only) ----------------
__device__ __forceinline__ uint32_t smem_u32(const void* p) {
    uint32_t a;
    asm("{ .reg .u64 t; cvta.to.shared.u64 t, %1; cvt.u32.u64 %0, t; }" : "=r"(a) : "l"(p));
    return a;
}
#define CP16(dst, src) \
    asm volatile("cp.async.cg.shared.global [%0], [%1], 16;" :: "r"(dst), "l"(src) : "memory")
#define CP_COMMIT() asm volatile("cp.async.commit_group;" ::: "memory")
#define CP_WAIT(n)  asm volatile("cp.async.wait_group %0;" :: "n"(n) : "memory")

__device__ __forceinline__ void ldsm_x4(uint32_t& r0, uint32_t& r1, uint32_t& r2, uint32_t& r3,
                                        uint32_t addr) {
    asm volatile("ldmatrix.sync.aligned.m8n8.x4.shared.b16 {%0,%1,%2,%3}, [%4];"
                 : "=r"(r0), "=r"(r1), "=r"(r2), "=r"(r3) : "r"(addr));
}
__device__ __forceinline__ void mma_f16(float* c, const uint32_t* a, uint32_t b0, uint32_t b1) {
    asm volatile("mma.sync.aligned.m16n8k16.row.col.f32.f16.f16.f32 "
                 "{%0,%1,%2,%3}, {%4,%5,%6,%7}, {%8,%9}, {%0,%1,%2,%3};"
                 : "+f"(c[0]), "+f"(c[1]), "+f"(c[2]), "+f"(c[3])
                 : "r"(a[0]), "r"(a[1]), "r"(a[2]), "r"(a[3]), "r"(b0), "r"(b1));
}

// ---------------- scratch (device globals) ----------------
__device__ int    g_count[NE];
__device__ int    g_list [NE * NTOK];     // token | (slot<<16)
__device__ float  g_plist[NE * NTOK];
__device__ int2   g_te[NTOK];
__device__ float2 g_tp[NTOK];
__device__ float  g_slots[2u * NTOK * DN];
__device__ float  g_expsum[NE];

__device__ __half g_xh [NTOK * HID];
__device__ __half g_dwh[NE * DN * HID];
__device__ __half g_uwh[HID * DN];
__device__ __half g_hh [NTOK * DN];

// ---------------- small kernels ----------------
__global__ void zero_counts_kernel() {
    if (threadIdx.x < NE) g_count[threadIdx.x] = 0;
}

__device__ __forceinline__ void conv4h(const float4 v, __half* dst, size_t i4) {
    __half2 a = __floats2half2_rn(v.x, v.y);
    __half2 b = __floats2half2_rn(v.z, v.w);
    ((uint2*)dst)[i4] = make_uint2(*(uint32_t*)&a, *(uint32_t*)&b);
}

__global__ void __launch_bounds__(256) conv_dw_kernel(const float* __restrict__ src) {
    size_t i = (size_t)blockIdx.x * blockDim.x + threadIdx.x;
    conv4h(((const float4*)src)[i], g_dwh, i);
}
__global__ void __launch_bounds__(256) conv_uw_kernel(const float* __restrict__ src) {
    size_t i = (size_t)blockIdx.x * blockDim.x + threadIdx.x;
    conv4h(((const float4*)src)[i], g_uwh, i);
}

// gate + fused x->fp16 conversion (x is staged through SMEM anyway)
__global__ void __launch_bounds__(128) gate_kernel(const float* __restrict__ x,
                                                   const float* __restrict__ gw) {
    __shared__ float xs[HID];
    __shared__ float logits[NE];
    const int t = blockIdx.x;
    const float* xr = x + (size_t)t * HID;
    __half* xh = g_xh + (size_t)t * HID;
    for (int i = threadIdx.x; i < HID / 4; i += blockDim.x) {
        float4 v = ((const float4*)xr)[i];
        ((float4*)xs)[i] = v;
        conv4h(v, xh, i);
    }
    __syncthreads();

    const int e = threadIdx.x >> 3;
    const int l = threadIdx.x & 7;
    const float* w = gw + (size_t)e * HID;
    float s = 0.f;
    for (int j = l; j < HID; j += 8) s += xs[j] * __ldg(w + j);
    for (int o = 4; o; o >>= 1) s += __shfl_down_sync(0xffffffffu, s, o, 8);
    if (l == 0) logits[e] = s;
    __syncthreads();

    if (threadIdx.x == 0) {
        float v0 = -1e30f; int i0 = 0;
        #pragma unroll
        for (int k = 0; k < NE; k++) { float v = logits[k]; if (v > v0) { v0 = v; i0 = k; } }
        float v1 = -1e30f; int i1 = 0;
        #pragma unroll
        for (int k = 0; k < NE; k++) { if (k == i0) continue; float v = logits[k]; if (v > v1) { v1 = v; i1 = k; } }
        float z  = expf(v1 - v0);
        float p0 = 1.f / (1.f + z);
        float p1 = z   / (1.f + z);

        int pos0 = atomicAdd(&g_count[i0], 1);
        g_list [i0 * NTOK + pos0] = t;
        g_plist[i0 * NTOK + pos0] = p0;
        int pos1 = atomicAdd(&g_count[i1], 1);
        g_list [i1 * NTOK + pos1] = t | (1 << 16);
        g_plist[i1 * NTOK + pos1] = p1;
        g_te[t] = make_int2(i0, i1);
        g_tp[t] = make_float2(p0, p1);
    }
}

__global__ void __launch_bounds__(256) expsum_kernel() {
    __shared__ float red[256];
    const int e = blockIdx.x;
    float s = 0.f;
    for (int t = threadIdx.x; t < NTOK; t += 256) {
        int2 te = g_te[t]; float2 tp = g_tp[t];
        if (te.x == e) s += tp.x;
        if (te.y == e) s += tp.y;
    }
    red[threadIdx.x] = s; __syncthreads();
    for (int o = 128; o; o >>= 1) {
        if (threadIdx.x < o) red[threadIdx.x] += red[threadIdx.x + o];
        __syncthreads();
    }
    if (threadIdx.x == 0) g_expsum[e] = red[0];
}

__device__ __forceinline__ float gelu_new(float v) {
    return 0.5f * v * (1.f + tanhf(0.7978845608028654f * (v + 0.044715f * v * v * v)));
}

__global__ void __launch_bounds__(256) gelu_kernel() {
    const size_t i = (size_t)blockIdx.x * blockDim.x + threadIdx.x;
    float4 a = ((const float4*)g_slots)[i];
    float4 b = ((const float4*)(g_slots + (size_t)NTOK * DN))[i];
    float4 r;
    r.x = gelu_new(a.x + b.x);
    r.y = gelu_new(a.y + b.y);
    r.z = gelu_new(a.z + b.z);
    r.w = gelu_new(a.w + b.w);
    conv4h(r, g_hh, i);
}

__global__ void loss_kernel(float* out, int out_size) {
    if (out_size > NTOK * HID) {
        float s = 0.f;
        #pragma unroll
        for (int e = 0; e < NE; e++) { float v = g_expsum[e]; s += v * v; }
        out[NTOK * HID] = (float)NE * 0.1f * s / ((float)NTOK * (float)NTOK);
    }
}

// ---------------- HMMA GEMM core ----------------
// Single pass over a 64-K chunk: C += A_tile(128x64) * B_tile(128x64)^T
// 8 warps; warp (wm, wn) owns rows wm*32..+32, cols wn*64..+64.
__device__ __forceinline__ void mma_pass(uint32_t aT, uint32_t bT, int lane, int wm, int wn,
                                         float C[2][8][4]) {
    const int g = lane >> 3, i = lane & 7;
    #pragma unroll
    for (int kk = 0; kk < 4; ++kk) {
        uint32_t af[2][4];
        #pragma unroll
        for (int mt = 0; mt < 2; ++mt) {
            int row  = wm * 32 + mt * 16 + i + (g & 1) * 8;
            int colb = kk * 32 + (g >> 1) * 16;
            ldsm_x4(af[mt][0], af[mt][1], af[mt][2], af[mt][3],
                    aT + SWZ((uint32_t)(row * 128 + colb)));
        }
        uint32_t bf[8][2];
        #pragma unroll
        for (int np = 0; np < 4; ++np) {
            int row  = wn * 64 + np * 16 + i + (g >> 1) * 8;
            int colb = kk * 32 + (g & 1) * 16;
            uint32_t r0, r1, r2, r3;
            ldsm_x4(r0, r1, r2, r3, bT + SWZ((uint32_t)(row * 128 + colb)));
            bf[np * 2][0] = r0; bf[np * 2][1] = r1;
            bf[np * 2 + 1][0] = r2; bf[np * 2 + 1][1] = r3;
        }
        #pragma unroll
        for (int mt = 0; mt < 2; ++mt)
            #pragma unroll
            for (int nt = 0; nt < 8; ++nt)
                mma_f16(C[mt][nt], af[mt], bf[nt][0], bf[nt][1]);
    }
}

// down: per expert e, C[m,n] = p_m * (x[tok_m] . dw[e][n] + db[e][n]) -> g_slots
__global__ void __launch_bounds__(256) down_mma_kernel(const float* __restrict__ db) {
    extern __shared__ __align__(1024) char smem[];
    const int e   = blockIdx.z;
    const int cnt = g_count[e];
    const int m0  = blockIdx.y * 128;
    if (m0 >= cnt) return;
    const int n0  = blockIdx.x * 128;

    const int tid  = threadIdx.x;
    const int lane = tid & 31;
    const int wid  = tid >> 5;
    const int wm   = wid >> 1;          // 0..3
    const int wn   = wid & 1;           // 0..1

    int*   smeta = (int*)(smem + SM_META);
    float* sp    = (float*)(smem + SM_P);
    if (tid < 128) {
        int m = m0 + tid;
        int v = 0; float p = 0.f;
        if (m < cnt) { v = g_list[e * NTOK + m]; p = g_plist[e * NTOK + m]; }
        smeta[tid] = v;
        sp[tid]    = p;
    }
    __syncthreads();

    const uint32_t sb = smem_u32(smem);
    const uint32_t tiles = sb + SM_TILES;

    auto load_stage = [&](int buf, int k0) {
        uint32_t st = tiles + buf * STAGE_B;
        #pragma unroll
        for (int q = 0; q < 4; ++q) {
            int u = tid + q * 256;
            int row = u >> 3, j = u & 7;
            int tok = smeta[row] & 0xffff;
            size_t src = (size_t)tok * HID + k0 + j * 8;
            uint32_t so = SWZ((uint32_t)(row * 128 + j * 16));
            CP16(st + so,          g_xh + src);
            size_t bsrc = ((size_t)e * DN + n0 + row) * HID + k0 + j * 8;
            CP16(st + TILE_B + so, g_dwh + bsrc);
        }
    };

    float C[2][8][4] = {};
    const int NCH = HID / BKC;   // 32

    load_stage(0, 0);
    CP_COMMIT();
    load_stage(1, BKC);
    CP_COMMIT();
    for (int c = 0; c < NCH; ++c) {
        if (c < NCH - 1) { CP_WAIT(1); } else { CP_WAIT(0); }
        __syncthreads();   // data(c) visible to all; all warps done reading buf[(c+2)%3]
        if (c + 2 < NCH) {
            load_stage((c + 2) % NSTAGE, (c + 2) * BKC);
            CP_COMMIT();
        }
        uint32_t st = tiles + (c % NSTAGE) * STAGE_B;
        mma_pass(st, st + TILE_B, lane, wm, wn, C);
    }

    // epilogue
    const float* dbp = db + (size_t)e * DN + n0 + wn * 64;
    #pragma unroll
    for (int mt = 0; mt < 2; ++mt) {
        #pragma unroll
        for (int half = 0; half < 2; ++half) {
            int rl = wm * 32 + mt * 16 + (lane >> 2) + half * 8;
            if (m0 + rl < cnt) {
                int   meta = smeta[rl];
                float p    = sp[rl];
                int tok = meta & 0xffff, slot = meta >> 16;
                float* dst = g_slots + ((size_t)slot * NTOK + tok) * DN + n0 + wn * 64;
                #pragma unroll
                for (int nt = 0; nt < 8; ++nt) {
                    int col = nt * 8 + (lane & 3) * 2;
                    float2 v;
                    v.x = p * (C[mt][nt][half * 2 + 0] + __ldg(dbp + col));
                    v.y = p * (C[mt][nt][half * 2 + 1] + __ldg(dbp + col + 1));
                    *(float2*)(dst + col) = v;
                }
            }
        }
    }
}

// up: out[m,n] = g_h[m] . up_w[n] + ub[n]   (M=8192, N=2048, K=512)
__global__ void __launch_bounds__(256) up_mma_kernel(const float* __restrict__ ub,
                                                     float* __restrict__ out) {
    extern __shared__ __align__(1024) char smem[];
    const int m0 = blockIdx.y * 128;
    const int n0 = blockIdx.x * 128;

    const int tid  = threadIdx.x;
    const int lane = tid & 31;
    const int wid  = tid >> 5;
    const int wm   = wid >> 1;
    const int wn   = wid & 1;

    const uint32_t sb = smem_u32(smem);
    const uint32_t tiles = sb + SM_TILES;

    auto load_stage = [&](int buf, int k0) {
        uint32_t st = tiles + buf * STAGE_B;
        #pragma unroll
        for (int q = 0; q < 4; ++q) {
            int u = tid + q * 256;
            int row = u >> 3, j = u & 7;
            size_t asrc = (size_t)(m0 + row) * DN + k0 + j * 8;
            size_t bsrc = (size_t)(n0 + row) * DN + k0 + j * 8;
            uint32_t so = SWZ((uint32_t)(row * 128 + j * 16));
            CP16(st + so,          g_hh + asrc);
            CP16(st + TILE_B + so, g_uwh + bsrc);
        }
    };

    float C[2][8][4] = {};
    const int NCH = DN / BKC;   // 8

    load_stage(0, 0);
    CP_COMMIT();
    load_stage(1, BKC);
    CP_COMMIT();
    for (int c = 0; c < NCH; ++c) {
        if (c < NCH - 1) { CP_WAIT(1); } else { CP_WAIT(0); }
        __syncthreads();
        if (c + 2 < NCH) {
            load_stage((c + 2) % NSTAGE, (c + 2) * BKC);
            CP_COMMIT();
        }
        uint32_t st = tiles + (c % NSTAGE) * STAGE_B;
        mma_pass(st, st + TILE_B, lane, wm, wn, C);
    }

    const float* ubp = ub + n0 + wn * 64;
    #pragma unroll
    for (int mt = 0; mt < 2; ++mt) {
        #pragma unroll
        for (int half = 0; half < 2; ++half) {
            int rl = wm * 32 + mt * 16 + (lane >> 2) + half * 8;
            float* dst = out + (size_t)(m0 + rl) * HID + n0 + wn * 64;
            #pragma unroll
            for (int nt = 0; nt < 8; ++nt) {
                int col = nt * 8 + (lane & 3) * 2;
                float2 v;
                v.x = C[mt][nt][half * 2 + 0] + __ldg(ubp + col);
                v.y = C[mt][nt][half * 2 + 1] + __ldg(ubp + col + 1);
                *(float2*)(dst + col) = v;
            }
        }
    }
}

// ---------------- launch ----------------
extern "C" void kernel_launch(void* const* d_in, const int* in_sizes, int n_in,
                              void* d_out, int out_size) {
    const float* x      = (const float*)d_in[0];
    const float* gate_w = (const float*)d_in[1];
    const float* down_w = (const float*)d_in[2];
    const float* down_b = (const float*)d_in[3];
    const float* up_w   = (const float*)d_in[4];
    const float* up_b   = (const float*)d_in[5];
    float* out = (float*)d_out;

    cudaFuncSetAttribute(down_mma_kernel, cudaFuncAttributeMaxDynamicSharedMemorySize, SMEM_BYTES);
    cudaFuncSetAttribute(up_mma_kernel,   cudaFuncAttributeMaxDynamicSharedMemorySize, SMEM_BYTES);

    zero_counts_kernel<<<1, 32>>>();
    conv_dw_kernel<<<(NE * DN * HID / 4) / 256, 256>>>(down_w);
    conv_uw_kernel<<<(HID * DN / 4) / 256, 256>>>(up_w);
    gate_kernel<<<NTOK, 128>>>(x, gate_w);
    expsum_kernel<<<NE, 256>>>();
    down_mma_kernel<<<dim3(DN / 128, NTOK / 128, NE), 256, SMEM_BYTES>>>(down_b);
    gelu_kernel<<<(NTOK * DN / 4) / 256, 256>>>();
    up_mma_kernel<<<dim3(HID / 128, NTOK / 128), 256, SMEM_BYTES>>>(up_b, out);
    loss_kernel<<<1, 1>>>(out, out_size);
}